// round 12
// baseline (speedup 1.0000x reference)
#include <cuda_runtime.h>
#include <cuda_fp16.h>
#include <cstdint>

#define SEQ 2048
#define DIM 128
#define BHN 32
#define NROWS (BHN * SEQ)   // 65536 rows each for q and k

// Normalized + sqrt(scale)-folded fp16 copies (16 MB each, device globals)
__device__ __half g_qh[(size_t)NROWS * DIM];
__device__ __half g_kh[(size_t)NROWS * DIM];

// ---------------------------------------------------------------------------
// Kernel 1: per-row normalize, fold sqrt(log2e/temp), convert to fp16.
// One warp per row.
// ---------------------------------------------------------------------------
__global__ void norm_cvt_kernel(const float* __restrict__ q,
                                const float* __restrict__ k,
                                const float* __restrict__ logt) {
    int gwarp = (blockIdx.x * blockDim.x + threadIdx.x) >> 5;
    int lane = threadIdx.x & 31;
    bool is_q = gwarp < NROWS;
    int row = is_q ? gwarp : gwarp - NROWS;
    const float* src = is_q ? q : k;
    float4 v = reinterpret_cast<const float4*>(src + (size_t)row * DIM)[lane];
    float ss = v.x * v.x + v.y * v.y + v.z * v.z + v.w * v.w;
#pragma unroll
    for (int o = 16; o > 0; o >>= 1) ss += __shfl_xor_sync(0xffffffffu, ss, o);

    const float LOG2E = 1.442695040888963f;
    float temp = fminf(fmaxf(__expf(*logt), 0.05f), 100.0f);
    float rsc = sqrtf(LOG2E / temp);
    float f = rsc / fmaxf(sqrtf(ss), 1e-12f);

    __half2 h0 = __floats2half2_rn(v.x * f, v.y * f);
    __half2 h1 = __floats2half2_rn(v.z * f, v.w * f);
    __half* dst = (is_q ? g_qh : g_kh) + (size_t)row * DIM + lane * 4;
    uint2 u;
    u.x = *reinterpret_cast<uint32_t*>(&h0);
    u.y = *reinterpret_cast<uint32_t*>(&h1);
    *reinterpret_cast<uint2*>(dst) = u;
}

// ---------------------------------------------------------------------------
// Helpers
// ---------------------------------------------------------------------------
__device__ __forceinline__ uint32_t smem_to_u32(const void* p) {
    uint32_t a;
    asm("{ .reg .u64 t; cvta.to.shared.u64 t, %1; cvt.u32.u64 %0, t; }" : "=r"(a) : "l"(p));
    return a;
}

// .ca: keep fills in L1 — co-resident CTAs and neighbor-bn CTAs share tiles
#define CP_ASYNC16(dst, src) \
    asm volatile("cp.async.ca.shared.global [%0], [%1], 16;" :: "r"(dst), "l"(src))
#define CP_COMMIT() asm volatile("cp.async.commit_group;" ::: "memory")
#define CP_WAIT(n)  asm volatile("cp.async.wait_group %0;" :: "n"(n) : "memory")

__device__ __forceinline__ void ldsm_x4(unsigned r[4], uint32_t addr) {
    asm volatile("ldmatrix.sync.aligned.m8n8.x4.shared.b16 {%0,%1,%2,%3}, [%4];"
                 : "=r"(r[0]), "=r"(r[1]), "=r"(r[2]), "=r"(r[3]) : "r"(addr));
}

__device__ __forceinline__ void mma_f16(float c[4], const unsigned a[4],
                                        unsigned b0, unsigned b1) {
    asm volatile(
        "mma.sync.aligned.m16n8k16.row.col.f32.f16.f16.f32 "
        "{%0,%1,%2,%3}, {%4,%5,%6,%7}, {%8,%9}, {%0,%1,%2,%3};\n"
        : "+f"(c[0]), "+f"(c[1]), "+f"(c[2]), "+f"(c[3])
        : "r"(a[0]), "r"(a[1]), "r"(a[2]), "r"(a[3]), "r"(b0), "r"(b1));
}

__device__ __forceinline__ float ex2f(float x) {
    float y;
    asm("ex2.approx.f32 %0, %1;" : "=f"(y) : "f"(x));
    return y;
}

// streaming store: output is written once, never re-read -> evict-first in L2
__device__ __forceinline__ void stg_cs_v2(float* p, float x, float y) {
    asm volatile("st.global.cs.v2.f32 [%0], {%1, %2};" :: "l"(p), "f"(x), "f"(y) : "memory");
}

// ---------------------------------------------------------------------------
// Kernel 2: fp16 GEMM + exp epilogue. 2 CTAs/SM, 256 threads.
// Each CTA computes TWO adjacent bn tiles (128x128 each), K=128 as 2 chunks
// of 64, THREE smem stages rotating t0c0->s0, t0c1->s1, t1c0->s2, t1c1->s0.
// Stage reuse needs no extra barriers: the refill target was drained before
// the program-order bar preceding the previous chunk's compute.
// Tile 0's epilogue overlaps tile 1's fills. One prologue per 2 tiles.
// Warp grid 2x4, warp tile 64x32. In-warp fragment double-buffering.
// smem: 3 stages x (A chunk 18432 + B chunk 18432) = 110592 B
//       -> 2 CTAs/SM (221184 <= 228K carveout).
// acc is in log2 domain (sqrt(scale) folded into both operands):
// epilogue = ex2(acc) + 1e-6.
// ---------------------------------------------------------------------------
#define LDH 72
#define CH_BYTES (128 * LDH * 2)          // 18432
#define STAGE_BYTES (2 * CH_BYTES)        // 36864
#define SMEM_TOTAL (3 * STAGE_BYTES)      // 110592

__global__ __launch_bounds__(256, 2) void hgemm_exp_kernel(float* __restrict__ out) {
    extern __shared__ char smem[];
    uint32_t sbase = smem_to_u32(smem);

    int bh = blockIdx.z;
    int bm = blockIdx.y;
    int bn0 = blockIdx.x * 2;     // pair of adjacent bn tiles
    int tid = threadIdx.x;
    int warp = tid >> 5, lane = tid & 31;
    int wm = warp >> 2, wn = warp & 3;   // 2 x 4 warp grid
    int wmo = wm * 64, wno = wn * 32;    // warp tile 64 x 32

    const __half* qb = g_qh + ((size_t)bh * SEQ + (size_t)bm * 128) * DIM;
    const __half* kb0 = g_kh + ((size_t)bh * SEQ + (size_t)bn0 * 128) * DIM;

    // cp.async: chunk matrix = 128 rows x 64 halves = 1024 16B-chunks -> 4/thr
    int ldr = tid >> 3;          // base row 0..31
    int ldc8 = tid & 7;          // 8-half column group

    // issue chunk c (0/1) of tile tt (0/1) into stage s
    auto issue_chunk = [&](int tt, int c, int s) {
        uint32_t stA = sbase + (uint32_t)(s * STAGE_BYTES);
        uint32_t stB = stA + CH_BYTES;
        const __half* qsrc = qb + c * 64 + ldc8 * 8;
        const __half* ksrc = kb0 + (size_t)tt * 128 * DIM + c * 64 + ldc8 * 8;
#pragma unroll
        for (int i = 0; i < 4; i++) {
            int r = ldr + i * 32;
            uint32_t o = (uint32_t)((r * LDH + ldc8 * 8) * 2);
            CP_ASYNC16(stA + o, qsrc + (size_t)r * DIM);
            CP_ASYNC16(stB + o, ksrc + (size_t)r * DIM);
        }
        CP_COMMIT();
    };

    issue_chunk(0, 0, 0);
    issue_chunk(0, 1, 1);

    // fragment offsets within a stage (halves*2 = bytes)
    int l15 = lane & 15, lk = (lane >> 4) * 8;
    uint32_t aOff[4], bOff[2];
#pragma unroll
    for (int mi = 0; mi < 4; mi++)
        aOff[mi] = (uint32_t)(((wmo + mi * 16 + l15) * LDH + lk) * 2);
#pragma unroll
    for (int p = 0; p < 2; p++)
        bOff[p] = (uint32_t)(((wno + p * 16 + l15) * LDH + lk) * 2) + CH_BYTES;

    float acc[4][4][4];
    unsigned af[2][4][4], bf[2][2][4];

    // compute one 64-deep chunk from stage s into acc
    auto compute_chunk = [&](int s) {
        uint32_t st = sbase + (uint32_t)(s * STAGE_BYTES);
        // prime step 0
#pragma unroll
        for (int mi = 0; mi < 4; mi++) ldsm_x4(af[0][mi], st + aOff[mi]);
#pragma unroll
        for (int p = 0; p < 2; p++) ldsm_x4(bf[0][p], st + bOff[p]);
#pragma unroll
        for (int ks = 0; ks < 4; ks++) {
            int cur = ks & 1, nxt = cur ^ 1;
            if (ks < 3) {
                uint32_t kb32 = (uint32_t)((ks + 1) * 32);
#pragma unroll
                for (int mi = 0; mi < 4; mi++) ldsm_x4(af[nxt][mi], st + aOff[mi] + kb32);
#pragma unroll
                for (int p = 0; p < 2; p++) ldsm_x4(bf[nxt][p], st + bOff[p] + kb32);
            }
#pragma unroll
            for (int mi = 0; mi < 4; mi++)
#pragma unroll
                for (int p = 0; p < 2; p++) {
                    mma_f16(acc[mi][2 * p],     af[cur][mi], bf[cur][p][0], bf[cur][p][2]);
                    mma_f16(acc[mi][2 * p + 1], af[cur][mi], bf[cur][p][1], bf[cur][p][3]);
                }
        }
    };

    // epilogue: out = ex2(acc) + 1e-6, streaming stores, strength-reduced ptrs
    int gid = lane >> 2, tig = lane & 3;
    auto epilogue = [&](int bn) {
        float* bp = out + ((size_t)bh * SEQ + (size_t)(bm * 128 + wmo + gid)) * SEQ
                        + bn * 128 + wno + tig * 2;
#pragma unroll
        for (int mi = 0; mi < 4; mi++) {
            float* o0p = bp;
            float* o1p = bp + (size_t)8 * SEQ;
#pragma unroll
            for (int ni = 0; ni < 4; ni++) {
                stg_cs_v2(o0p, ex2f(acc[mi][ni][0]) + 1e-6f,
                               ex2f(acc[mi][ni][1]) + 1e-6f);
                stg_cs_v2(o1p, ex2f(acc[mi][ni][2]) + 1e-6f,
                               ex2f(acc[mi][ni][3]) + 1e-6f);
                o0p += 8; o1p += 8;
            }
            bp += (size_t)16 * SEQ;
        }
    };

    auto zero_acc = [&]() {
#pragma unroll
        for (int mi = 0; mi < 4; mi++)
#pragma unroll
            for (int ni = 0; ni < 4; ni++)
#pragma unroll
                for (int r = 0; r < 4; r++) acc[mi][ni][r] = 0.0f;
    };

    // ---- tile 0 ----
    zero_acc();
    CP_WAIT(1);
    __syncthreads();
    compute_chunk(0);
    issue_chunk(1, 0, 2);          // s2 untouched: no barrier needed

    CP_WAIT(1);
    __syncthreads();               // also proves all warps drained s0
    compute_chunk(1);
    issue_chunk(1, 1, 0);          // s0 refill: safe per barrier above

    epilogue(bn0);                 // overlaps tile-1 fills

    // ---- tile 1 ----
    zero_acc();
    CP_WAIT(1);
    __syncthreads();
    compute_chunk(2);

    CP_WAIT(0);
    __syncthreads();
    compute_chunk(0);

    epilogue(bn0 + 1);
}

// ---------------------------------------------------------------------------
// Launcher (graph-capturable: kernel launches only)
// ---------------------------------------------------------------------------
extern "C" void kernel_launch(void* const* d_in, const int* in_sizes, int n_in,
                              void* d_out, int out_size) {
    const float* q  = (const float*)d_in[0];
    const float* k  = (const float*)d_in[1];
    const float* lt = (const float*)d_in[2];
    float* out = (float*)d_out;

    norm_cvt_kernel<<<(2 * NROWS) / 8, 256>>>(q, k, lt);

    cudaFuncSetAttribute(hgemm_exp_kernel,
                         cudaFuncAttributeMaxDynamicSharedMemorySize, SMEM_TOTAL);
    dim3 grid(8, 16, 32);  // (bn-pair, bm, bh)
    hgemm_exp_kernel<<<grid, 256, SMEM_TOTAL>>>(out);
}

// round 13
// speedup vs baseline: 1.1234x; 1.1234x over previous
#include <cuda_runtime.h>
#include <cuda_fp16.h>
#include <cstdint>

#define SEQ 2048
#define DIM 128
#define BHN 32
#define NROWS (BHN * SEQ)   // 65536 rows each for q and k

// Normalized + sqrt(scale)-folded fp16 copies (16 MB each, device globals)
__device__ __half g_qh[(size_t)NROWS * DIM];
__device__ __half g_kh[(size_t)NROWS * DIM];

// ---------------------------------------------------------------------------
// Kernel 1: per-row normalize, fold sqrt(log2e/temp), convert to fp16.
// One warp per row.
// ---------------------------------------------------------------------------
__global__ void norm_cvt_kernel(const float* __restrict__ q,
                                const float* __restrict__ k,
                                const float* __restrict__ logt) {
    int gwarp = (blockIdx.x * blockDim.x + threadIdx.x) >> 5;
    int lane = threadIdx.x & 31;
    bool is_q = gwarp < NROWS;
    int row = is_q ? gwarp : gwarp - NROWS;
    const float* src = is_q ? q : k;
    float4 v = reinterpret_cast<const float4*>(src + (size_t)row * DIM)[lane];
    float ss = v.x * v.x + v.y * v.y + v.z * v.z + v.w * v.w;
#pragma unroll
    for (int o = 16; o > 0; o >>= 1) ss += __shfl_xor_sync(0xffffffffu, ss, o);

    const float LOG2E = 1.442695040888963f;
    float temp = fminf(fmaxf(__expf(*logt), 0.05f), 100.0f);
    float rsc = sqrtf(LOG2E / temp);
    float f = rsc / fmaxf(sqrtf(ss), 1e-12f);

    __half2 h0 = __floats2half2_rn(v.x * f, v.y * f);
    __half2 h1 = __floats2half2_rn(v.z * f, v.w * f);
    __half* dst = (is_q ? g_qh : g_kh) + (size_t)row * DIM + lane * 4;
    uint2 u;
    u.x = *reinterpret_cast<uint32_t*>(&h0);
    u.y = *reinterpret_cast<uint32_t*>(&h1);
    *reinterpret_cast<uint2*>(dst) = u;
}

// ---------------------------------------------------------------------------
// Helpers
// ---------------------------------------------------------------------------
__device__ __forceinline__ uint32_t smem_to_u32(const void* p) {
    uint32_t a;
    asm("{ .reg .u64 t; cvta.to.shared.u64 t, %1; cvt.u32.u64 %0, t; }" : "=r"(a) : "l"(p));
    return a;
}

// .ca: keep fills in L1 — co-resident CTAs and neighbor-bn CTAs share tiles
#define CP_ASYNC16(dst, src) \
    asm volatile("cp.async.ca.shared.global [%0], [%1], 16;" :: "r"(dst), "l"(src))
#define CP_COMMIT() asm volatile("cp.async.commit_group;" ::: "memory")
#define CP_WAIT(n)  asm volatile("cp.async.wait_group %0;" :: "n"(n) : "memory")

__device__ __forceinline__ void ldsm_x4(unsigned r[4], uint32_t addr) {
    asm volatile("ldmatrix.sync.aligned.m8n8.x4.shared.b16 {%0,%1,%2,%3}, [%4];"
                 : "=r"(r[0]), "=r"(r[1]), "=r"(r[2]), "=r"(r[3]) : "r"(addr));
}

__device__ __forceinline__ void mma_f16(float c[4], const unsigned a[4],
                                        unsigned b0, unsigned b1) {
    asm volatile(
        "mma.sync.aligned.m16n8k16.row.col.f32.f16.f16.f32 "
        "{%0,%1,%2,%3}, {%4,%5,%6,%7}, {%8,%9}, {%0,%1,%2,%3};\n"
        : "+f"(c[0]), "+f"(c[1]), "+f"(c[2]), "+f"(c[3])
        : "r"(a[0]), "r"(a[1]), "r"(a[2]), "r"(a[3]), "r"(b0), "r"(b1));
}

__device__ __forceinline__ float ex2f(float x) {
    float y;
    asm("ex2.approx.f32 %0, %1;" : "=f"(y) : "f"(x));
    return y;
}

// streaming store: output is written once, never re-read -> evict-first in L2
__device__ __forceinline__ void stg_cs_v2(float* p, float x, float y) {
    asm volatile("st.global.cs.v2.f32 [%0], {%1, %2};" :: "l"(p), "f"(x), "f"(y) : "memory");
}

// ---------------------------------------------------------------------------
// Kernel 2: fp16 GEMM + exp epilogue. 2 CTAs/SM, 256 threads.
// CTA tile: M=128 x N=128, K=128 in two chunks of 64, 2 smem stages.
// Warp grid 2x4, warp tile 64x32 (acc 64 regs/lane).
// In-warp fragment software pipeline (k-step s+1 LDSM under step s MMAs).
// FUSED TAIL: the last k-step interleaves per-mi epilogues (ex2 + stg.cs)
// with the remaining mi MMA groups, one mi behind, so MUFU/STG issue while
// the tensor pipe retires the final MMAs.
// smem chunk row = 72 halves (144 B): conflict-free ldmatrix pointers.
// Stage = A chunk + B chunk = 36864 B. Total 73728 B -> 2 CTAs/SM.
// acc is in log2 domain (sqrt(scale) folded into both operands):
// epilogue = ex2(acc) + 1e-6.
// ---------------------------------------------------------------------------
#define LDH 72
#define CH_BYTES (128 * LDH * 2)          // 18432
#define STAGE_BYTES (2 * CH_BYTES)        // 36864
#define SMEM_TOTAL (2 * STAGE_BYTES)      // 73728

__global__ __launch_bounds__(256, 2) void hgemm_exp_kernel(float* __restrict__ out) {
    extern __shared__ char smem[];
    uint32_t sbase = smem_to_u32(smem);

    int bh = blockIdx.z;
    int bm = blockIdx.y;
    int bn = blockIdx.x;
    int tid = threadIdx.x;
    int warp = tid >> 5, lane = tid & 31;
    int wm = warp >> 2, wn = warp & 3;   // 2 x 4 warp grid
    int wmo = wm * 64, wno = wn * 32;    // warp tile 64 x 32

    const __half* qb = g_qh + ((size_t)bh * SEQ + (size_t)bm * 128) * DIM;
    const __half* kb = g_kh + ((size_t)bh * SEQ + (size_t)bn * 128) * DIM;

    // cp.async: chunk matrix = 128 rows x 64 halves = 1024 16B-chunks -> 4/thr
    int ldr = tid >> 3;          // base row 0..31
    int ldc8 = tid & 7;          // 8-half column group

    auto issue_chunk = [&](int c, int s) {
        uint32_t stA = sbase + (uint32_t)(s * STAGE_BYTES);
        uint32_t stB = stA + CH_BYTES;
        const __half* qsrc = qb + c * 64 + ldc8 * 8;
        const __half* ksrc = kb + c * 64 + ldc8 * 8;
#pragma unroll
        for (int i = 0; i < 4; i++) {
            int r = ldr + i * 32;
            uint32_t o = (uint32_t)((r * LDH + ldc8 * 8) * 2);
            CP_ASYNC16(stA + o, qsrc + (size_t)r * DIM);
            CP_ASYNC16(stB + o, ksrc + (size_t)r * DIM);
        }
        CP_COMMIT();
    };

    issue_chunk(0, 0);
    issue_chunk(1, 1);

    // fragment offsets within a stage (halves*2 = bytes)
    int l15 = lane & 15, lk = (lane >> 4) * 8;
    uint32_t aOff[4], bOff[2];
#pragma unroll
    for (int mi = 0; mi < 4; mi++)
        aOff[mi] = (uint32_t)(((wmo + mi * 16 + l15) * LDH + lk) * 2);
#pragma unroll
    for (int p = 0; p < 2; p++)
        bOff[p] = (uint32_t)(((wno + p * 16 + l15) * LDH + lk) * 2) + CH_BYTES;

    float acc[4][4][4];
#pragma unroll
    for (int mi = 0; mi < 4; mi++)
#pragma unroll
        for (int ni = 0; ni < 4; ni++)
#pragma unroll
            for (int r = 0; r < 4; r++) acc[mi][ni][r] = 0.0f;

    unsigned af[2][4][4], bf[2][2][4];

    // per-mi MMA group for k-step buffer `cur`
    auto mma_mi = [&](int cur, int mi) {
#pragma unroll
        for (int p = 0; p < 2; p++) {
            mma_f16(acc[mi][2 * p],     af[cur][mi], bf[cur][p][0], bf[cur][p][2]);
            mma_f16(acc[mi][2 * p + 1], af[cur][mi], bf[cur][p][1], bf[cur][p][3]);
        }
    };

    // epilogue store base: row (bm*128 + wmo + gid), col (bn*128 + wno + tig*2)
    int gid = lane >> 2, tig = lane & 3;
    float* bp = out + ((size_t)bh * SEQ + (size_t)(bm * 128 + wmo + gid)) * SEQ
                    + bn * 128 + wno + tig * 2;

    // per-mi epilogue: 16 ex2 + 8 stg.cs.v2
    auto epi_mi = [&](int mi) {
        float* o0p = bp + (size_t)(mi * 16) * SEQ;
        float* o1p = o0p + (size_t)8 * SEQ;
#pragma unroll
        for (int ni = 0; ni < 4; ni++) {
            stg_cs_v2(o0p, ex2f(acc[mi][ni][0]) + 1e-6f,
                           ex2f(acc[mi][ni][1]) + 1e-6f);
            stg_cs_v2(o1p, ex2f(acc[mi][ni][2]) + 1e-6f,
                           ex2f(acc[mi][ni][3]) + 1e-6f);
            o0p += 8; o1p += 8;
        }
    };

    // ---- chunk 0: 4 ksteps, fragments pipelined one step ahead ----
    CP_WAIT(1);
    __syncthreads();
    {
        uint32_t st = sbase;
#pragma unroll
        for (int mi = 0; mi < 4; mi++) ldsm_x4(af[0][mi], st + aOff[mi]);
#pragma unroll
        for (int p = 0; p < 2; p++) ldsm_x4(bf[0][p], st + bOff[p]);
#pragma unroll
        for (int s = 0; s < 4; s++) {
            int cur = s & 1, nxt = cur ^ 1;
            if (s < 3) {
                uint32_t kb32 = (uint32_t)((s + 1) * 32);
#pragma unroll
                for (int mi = 0; mi < 4; mi++) ldsm_x4(af[nxt][mi], st + aOff[mi] + kb32);
#pragma unroll
                for (int p = 0; p < 2; p++) ldsm_x4(bf[nxt][p], st + bOff[p] + kb32);
            }
#pragma unroll
            for (int mi = 0; mi < 4; mi++) mma_mi(cur, mi);
        }
    }

    // ---- chunk 1: ksteps 0-2 normal, kstep 3 fused with epilogue ----
    CP_WAIT(0);
    __syncthreads();
    {
        uint32_t st = sbase + STAGE_BYTES;
#pragma unroll
        for (int mi = 0; mi < 4; mi++) ldsm_x4(af[0][mi], st + aOff[mi]);
#pragma unroll
        for (int p = 0; p < 2; p++) ldsm_x4(bf[0][p], st + bOff[p]);
#pragma unroll
        for (int s = 0; s < 3; s++) {
            int cur = s & 1, nxt = cur ^ 1;
            uint32_t kb32 = (uint32_t)((s + 1) * 32);
#pragma unroll
            for (int mi = 0; mi < 4; mi++) ldsm_x4(af[nxt][mi], st + aOff[mi] + kb32);
#pragma unroll
            for (int p = 0; p < 2; p++) ldsm_x4(bf[nxt][p], st + bOff[p] + kb32);
#pragma unroll
            for (int mi = 0; mi < 4; mi++) mma_mi(cur, mi);
        }
        // kstep 3 (buffer 1): interleave epilogue one mi behind the MMAs
        mma_mi(1, 0);
        mma_mi(1, 1);
        epi_mi(0);
        mma_mi(1, 2);
        epi_mi(1);
        mma_mi(1, 3);
        epi_mi(2);
        epi_mi(3);
    }
}

// ---------------------------------------------------------------------------
// Launcher (graph-capturable: kernel launches only)
// ---------------------------------------------------------------------------
extern "C" void kernel_launch(void* const* d_in, const int* in_sizes, int n_in,
                              void* d_out, int out_size) {
    const float* q  = (const float*)d_in[0];
    const float* k  = (const float*)d_in[1];
    const float* lt = (const float*)d_in[2];
    float* out = (float*)d_out;

    norm_cvt_kernel<<<(2 * NROWS) / 8, 256>>>(q, k, lt);

    cudaFuncSetAttribute(hgemm_exp_kernel,
                         cudaFuncAttributeMaxDynamicSharedMemorySize, SMEM_TOTAL);
    dim3 grid(16, 16, 32);  // (bn, bm, bh)
    hgemm_exp_kernel<<<grid, 256, SMEM_TOTAL>>>(out);
}